// round 14
// baseline (speedup 1.0000x reference)
#include <cuda_runtime.h>
#include <cuda_bf16.h>
#include <cstdint>

#define BATCH 4
#define DDIM  1024
#define NSEQ  2048
#define KDIM  1024

typedef __nv_bfloat16 bf16;

// ---------------- scratch (device globals; zero-init bss) -------------------
__device__ bf16 g_Xhi [BATCH * DDIM * NSEQ], g_Xlo [BATCH * DDIM * NSEQ];   // (b,d,n)
__device__ bf16 g_XThi[BATCH * NSEQ * DDIM], g_XTlo[BATCH * NSEQ * DDIM];   // (b,i,d)
__device__ bf16 g_WQhi[KDIM * DDIM], g_WQlo[KDIM * DDIM];                   // (k,d)
__device__ bf16 g_WKhi[KDIM * DDIM], g_WKlo[KDIM * DDIM];
__device__ bf16 g_WOThi[DDIM * KDIM], g_WOTlo[DDIM * KDIM];                 // (d,k)
__device__ bf16 g_WVThi[DDIM * KDIM], g_WVTlo[DDIM * KDIM];                 // (e,k)
__device__ bf16 g_qhi [BATCH * NSEQ * KDIM], g_qlo [BATCH * NSEQ * KDIM];   // (b,i,k)
__device__ bf16 g_khi [BATCH * NSEQ * KDIM], g_klo [BATCH * NSEQ * KDIM];   // (b,j,k)
__device__ bf16 g_Mhi [DDIM * DDIM], g_Mlo [DDIM * DDIM];                   // (d,e)
__device__ float g_L  [BATCH * NSEQ * NSEQ];                                // logits fp32
__device__ bf16 g_Ahi [BATCH * NSEQ * NSEQ], g_Alo [BATCH * NSEQ * NSEQ];   // softmax out
__device__ bf16 g_cthi[BATCH * NSEQ * DDIM], g_ctlo[BATCH * NSEQ * DDIM];   // (b,i,e)

// ---------------- helpers ----------------------------------------------------
__device__ __forceinline__ uint32_t smem_u32(const void* p) {
    uint32_t a;
    asm("{ .reg .u64 t; cvta.to.shared.u64 t, %1; cvt.u32.u64 %0, t; }" : "=r"(a) : "l"(p));
    return a;
}
__device__ __forceinline__ void ldsm4(uint32_t* r, uint32_t addr) {
    asm volatile("ldmatrix.sync.aligned.m8n8.x4.shared.b16 {%0,%1,%2,%3}, [%4];"
                 : "=r"(r[0]), "=r"(r[1]), "=r"(r[2]), "=r"(r[3]) : "r"(addr));
}
__device__ __forceinline__ void mma16816(float* d, const uint32_t* a, const uint32_t* b) {
    asm volatile(
        "mma.sync.aligned.m16n8k16.row.col.f32.bf16.bf16.f32 "
        "{%0,%1,%2,%3}, {%4,%5,%6,%7}, {%8,%9}, {%0,%1,%2,%3};"
        : "+f"(d[0]), "+f"(d[1]), "+f"(d[2]), "+f"(d[3])
        : "r"(a[0]), "r"(a[1]), "r"(a[2]), "r"(a[3]), "r"(b[0]), "r"(b[1]));
}
__device__ __forceinline__ void cpasync16(uint32_t dst, const void* src) {
    asm volatile("cp.async.cg.shared.global [%0], [%1], 16;" :: "r"(dst), "l"(src));
}
__device__ __forceinline__ void cp_commit() { asm volatile("cp.async.commit_group;"); }
__device__ __forceinline__ void cp_wait1()  { asm volatile("cp.async.wait_group 1;"); }

__device__ __forceinline__ uint32_t pack_hi(float a, float b) {
    bf16 h0 = __float2bfloat16(a), h1 = __float2bfloat16(b);
    return (uint32_t)__bfloat16_as_ushort(h0) | ((uint32_t)__bfloat16_as_ushort(h1) << 16);
}
__device__ __forceinline__ uint32_t pack_lo(float a, float b) {
    bf16 h0 = __float2bfloat16(a), h1 = __float2bfloat16(b);
    float l0 = a - __bfloat162float(h0), l1 = b - __bfloat162float(h1);
    return (uint32_t)__bfloat16_as_ushort(__float2bfloat16(l0)) |
           ((uint32_t)__bfloat16_as_ushort(__float2bfloat16(l1)) << 16);
}

// ---------------- convert fp32 -> bf16 hi/lo --------------------------------
__global__ void convert_hl(const float* __restrict__ in, bf16* __restrict__ hi,
                           bf16* __restrict__ lo, long long n) {
    long long i = ((long long)blockIdx.x * blockDim.x + threadIdx.x) * 4;
    if (i >= n) return;
    float4 v = *(const float4*)(in + i);
    *(uint2*)(hi + i) = make_uint2(pack_hi(v.x, v.y), pack_hi(v.z, v.w));
    *(uint2*)(lo + i) = make_uint2(pack_lo(v.x, v.y), pack_lo(v.z, v.w));
}

// ---------------- transpose fp32 -> bf16 hi/lo ------------------------------
__global__ void transpose_hl(const float* __restrict__ in, bf16* __restrict__ hi,
                             bf16* __restrict__ lo, int rows, int cols,
                             long long sIn, long long sOut) {
    __shared__ float tile[32][33];
    const float* I = in + (long long)blockIdx.z * sIn;
    int r0 = blockIdx.y * 32, c0 = blockIdx.x * 32;
    int x = threadIdx.x, y = threadIdx.y;
#pragma unroll
    for (int j = y; j < 32; j += 8)
        tile[j][x] = I[(long long)(r0 + j) * cols + c0 + x];
    __syncthreads();
    long long zo = (long long)blockIdx.z * sOut;
#pragma unroll
    for (int j = y; j < 32; j += 8) {
        float v = tile[x][j];
        long long o = zo + (long long)(c0 + j) * rows + r0 + x;
        bf16 h = __float2bfloat16(v);
        hi[o] = h;
        lo[o] = __float2bfloat16(v - __bfloat162float(h));
    }
}

// ---------------- fused X: convert + transpose, vectorized u32 stores -------
__global__ void convtrans_X(const float* __restrict__ in,
                            bf16* __restrict__ hi, bf16* __restrict__ lo,
                            bf16* __restrict__ thi, bf16* __restrict__ tlo) {
    __shared__ float tile[32][33];
    long long zb = (long long)blockIdx.z * DDIM * NSEQ;
    int r0 = blockIdx.y * 32, c0 = blockIdx.x * 32;
    int tid = threadIdx.y * 32 + threadIdx.x;
    int l = tid & 15, g = tid >> 4;
#pragma unroll
    for (int it = 0; it < 2; ++it) {
        int j = g + it * 16;
        long long o = zb + (long long)(r0 + j) * NSEQ + c0 + 2 * l;
        float2 v = *(const float2*)(in + o);
        tile[j][2 * l]     = v.x;
        tile[j][2 * l + 1] = v.y;
        *(uint32_t*)(hi + o) = pack_hi(v.x, v.y);
        *(uint32_t*)(lo + o) = pack_lo(v.x, v.y);
    }
    __syncthreads();
#pragma unroll
    for (int it = 0; it < 2; ++it) {
        int j = g + it * 16;
        float a = tile[2 * l][j], b2 = tile[2 * l + 1][j];
        long long o = zb + (long long)(c0 + j) * DDIM + r0 + 2 * l;
        *(uint32_t*)(thi + o) = pack_hi(a, b2);
        *(uint32_t*)(tlo + o) = pack_lo(a, b2);
    }
}

// ---------------- bf16 hi/lo HMMA NT GEMM -----------------------------------
// C[m][n] = sum_k A[m][k]*B[n][k]; A rows have leading dim ldA, B rows ldB.
// Inner loop restructured: M processed in 2 halves of 2 m-tiles to keep peak
// live fragments at 32 regs (vs 48) -> no spills under the 128-reg/2-CTA cap.
#define TM 128
#define TN 128
#define KC 32
#define TILE_B 8192
#define STAGE_B (4 * TILE_B)
#define STAGES 3
#define GSMEM (STAGES * STAGE_B)

__global__ void __launch_bounds__(256, 2)
hgemm(const bf16* __restrict__ Ahi_, const bf16* __restrict__ Alo_,
      const bf16* __restrict__ Bhi_, const bf16* __restrict__ Blo_,
      float* __restrict__ Cf, bf16* __restrict__ Chi, bf16* __restrict__ Clo,
      const float* __restrict__ Res,
      int M, int N, int Kk, int ldA, int ldB,
      long long sA, long long sB, long long sC, long long sRes,
      int causal, int kcap, int m_off, int n_off) {
    int by = (causal || kcap) ? (gridDim.y - 1 - blockIdx.y) : blockIdx.y;
    int m0 = m_off + by * TM;
    int n0 = n_off + blockIdx.x * TN;
    if (causal && n0 > m0 + TM - 1) return;

    extern __shared__ char sm[];
    uint32_t sb = smem_u32(sm);
    int tid = threadIdx.x, lane = tid & 31, wid = tid >> 5;
    int wm = wid & 1, wn = wid >> 1;
    long long z = blockIdx.z;

    int row = tid >> 1, seg0 = (tid & 1) * 2;
    int ssw = (row >> 1) & 3;
    uint32_t so0 = (uint32_t)(row * 64 + ((seg0 ^ ssw) << 4));
    uint32_t so1 = (uint32_t)(row * 64 + (((seg0 + 1) ^ ssw) << 4));
    const bf16* pAhi = Ahi_ + z * sA + (long long)(m0 + row) * ldA + seg0 * 8;
    const bf16* pAlo = Alo_ + z * sA + (long long)(m0 + row) * ldA + seg0 * 8;
    const bf16* pBhi = Bhi_ + z * sB + (long long)(n0 + row) * ldB + seg0 * 8;
    const bf16* pBlo = Blo_ + z * sB + (long long)(n0 + row) * ldB + seg0 * 8;

    int ra = wm * 64 + (lane & 15);
    int abit = lane >> 4;
    uint32_t aRow = (uint32_t)ra * 64;
    int swA = (ra >> 1) & 3;
    uint32_t colA[2] = { (uint32_t)(((0 + abit) ^ swA) << 4),
                         (uint32_t)(((2 + abit) ^ swA) << 4) };
    int rb = wn * 32 + ((lane >> 4) << 3) + (lane & 7);
    int bbit = (lane >> 3) & 1;
    uint32_t bRow = (uint32_t)rb * 64;
    int swB = (rb >> 1) & 3;
    uint32_t colB[2] = { (uint32_t)(((0 + bbit) ^ swB) << 4),
                         (uint32_t)(((2 + bbit) ^ swB) << 4) };

    float acc[4][4][4];
#pragma unroll
    for (int mt = 0; mt < 4; ++mt)
#pragma unroll
        for (int nt = 0; nt < 4; ++nt)
#pragma unroll
            for (int r = 0; r < 4; ++r) acc[mt][nt][r] = 0.f;

    int KkE = kcap ? (m0 + TM < Kk ? m0 + TM : Kk) : Kk;
    const int nc = KkE / KC;

#pragma unroll
    for (int s = 0; s < STAGES - 1; ++s) {
        long long off = (long long)s * KC;
        uint32_t d = sb + s * STAGE_B;
        cpasync16(d + 0 * TILE_B + so0, pAhi + off);
        cpasync16(d + 0 * TILE_B + so1, pAhi + off + 8);
        cpasync16(d + 1 * TILE_B + so0, pAlo + off);
        cpasync16(d + 1 * TILE_B + so1, pAlo + off + 8);
        cpasync16(d + 2 * TILE_B + so0, pBhi + off);
        cpasync16(d + 2 * TILE_B + so1, pBhi + off + 8);
        cpasync16(d + 3 * TILE_B + so0, pBlo + off);
        cpasync16(d + 3 * TILE_B + so1, pBlo + off + 8);
        cp_commit();
    }

    for (int c = 0; c < nc; ++c) {
        cp_wait1();
        __syncthreads();
        if (c + 2 < nc) {
            int st = (c + 2) % STAGES;
            long long off = (long long)(c + 2) * KC;
            uint32_t d = sb + st * STAGE_B;
            cpasync16(d + 0 * TILE_B + so0, pAhi + off);
            cpasync16(d + 0 * TILE_B + so1, pAhi + off + 8);
            cpasync16(d + 1 * TILE_B + so0, pAlo + off);
            cpasync16(d + 1 * TILE_B + so1, pAlo + off + 8);
            cpasync16(d + 2 * TILE_B + so0, pBhi + off);
            cpasync16(d + 2 * TILE_B + so1, pBhi + off + 8);
            cpasync16(d + 3 * TILE_B + so0, pBlo + off);
            cpasync16(d + 3 * TILE_B + so1, pBlo + off + 8);
            cp_commit();
        } else {
            cp_commit();
        }

        uint32_t bA = sb + (c % STAGES) * STAGE_B;
        uint32_t bAhi = bA, bAlo = bA + TILE_B, bBhi = bA + 2 * TILE_B, bBlo = bA + 3 * TILE_B;

#pragma unroll
        for (int kk2 = 0; kk2 < 2; ++kk2) {
            // B fragments loaded once, shared across both m-halves
            uint32_t bh[4][2], bl[4][2];
#pragma unroll
            for (int jp = 0; jp < 2; ++jp) {
                uint32_t r[4];
                ldsm4(r, bBhi + bRow + jp * 1024 + colB[kk2]);
                bh[2 * jp][0] = r[0]; bh[2 * jp][1] = r[1];
                bh[2 * jp + 1][0] = r[2]; bh[2 * jp + 1][1] = r[3];
            }
#pragma unroll
            for (int jp = 0; jp < 2; ++jp) {
                uint32_t r[4];
                ldsm4(r, bBlo + bRow + jp * 1024 + colB[kk2]);
                bl[2 * jp][0] = r[0]; bl[2 * jp][1] = r[1];
                bl[2 * jp + 1][0] = r[2]; bl[2 * jp + 1][1] = r[3];
            }
            // M in two halves of 2 m-tiles: peak live frags = bh+bl+ah2+al2 = 32
#pragma unroll
            for (int mh = 0; mh < 2; ++mh) {
                uint32_t ah[2][4], al[2][4];
#pragma unroll
                for (int m2 = 0; m2 < 2; ++m2)
                    ldsm4(ah[m2], bAhi + aRow + (mh * 2 + m2) * 1024 + colA[kk2]);
#pragma unroll
                for (int m2 = 0; m2 < 2; ++m2)
#pragma unroll
                    for (int nt = 0; nt < 4; ++nt)
                        mma16816(acc[mh * 2 + m2][nt], ah[m2], bh[nt]);
#pragma unroll
                for (int m2 = 0; m2 < 2; ++m2)
                    ldsm4(al[m2], bAlo + aRow + (mh * 2 + m2) * 1024 + colA[kk2]);
#pragma unroll
                for (int m2 = 0; m2 < 2; ++m2)
#pragma unroll
                    for (int nt = 0; nt < 4; ++nt)
                        mma16816(acc[mh * 2 + m2][nt], ah[m2], bl[nt]);
#pragma unroll
                for (int m2 = 0; m2 < 2; ++m2)
#pragma unroll
                    for (int nt = 0; nt < 4; ++nt)
                        mma16816(acc[mh * 2 + m2][nt], al[m2], bh[nt]);
            }
        }
    }

    int er = lane >> 2, ec = (lane & 3) * 2;
    if (Cf) {
        float* Cb = Cf + z * sC;
        const float* Rb = Res ? Res + z * sRes : nullptr;
#pragma unroll
        for (int mt = 0; mt < 4; ++mt) {
#pragma unroll
            for (int nt = 0; nt < 4; ++nt) {
                long long r0 = (long long)(m0 + wm * 64 + mt * 16 + er);
                int col = n0 + wn * 32 + nt * 8 + ec;
                float2 v0 = make_float2(acc[mt][nt][0], acc[mt][nt][1]);
                float2 v1 = make_float2(acc[mt][nt][2], acc[mt][nt][3]);
                if (Rb) {
                    float2 q0 = *(const float2*)(Rb + r0 * N + col);
                    float2 q1 = *(const float2*)(Rb + (r0 + 8) * N + col);
                    v0.x += q0.x; v0.y += q0.y; v1.x += q1.x; v1.y += q1.y;
                }
                *(float2*)(Cb + r0 * N + col)       = v0;
                *(float2*)(Cb + (r0 + 8) * N + col) = v1;
            }
        }
    } else {
        bf16* Hb = Chi + z * sC;
        bf16* Lb = Clo + z * sC;
#pragma unroll
        for (int mt = 0; mt < 4; ++mt) {
#pragma unroll
            for (int nt = 0; nt < 4; ++nt) {
                long long r0 = (long long)(m0 + wm * 64 + mt * 16 + er);
                int col = n0 + wn * 32 + nt * 8 + ec;
#pragma unroll
                for (int h = 0; h < 2; ++h) {
                    float v0 = acc[mt][nt][2 * h], v1 = acc[mt][nt][2 * h + 1];
                    long long o = (r0 + 8 * h) * N + col;
                    *(uint32_t*)(Hb + o) = pack_hi(v0, v1);
                    *(uint32_t*)(Lb + o) = pack_lo(v0, v1);
                }
            }
        }
    }
}

// ---------------- row softmax: online max+sum (2 passes), causal ------------
__global__ void softmax_rows(const float* __restrict__ L, bf16* __restrict__ Ahi,
                             bf16* __restrict__ Alo, int Nn, int i_off) {
    int b = blockIdx.y, i = i_off + blockIdx.x;
    const float* row = L + ((long long)b * Nn + i) * Nn;
    bf16* ah = Ahi + ((long long)b * Nn + i) * Nn;
    bf16* al = Alo + ((long long)b * Nn + i) * Nn;
    int nv = i + 1;
    int t = threadIdx.x;
    __shared__ float redm[256], reds[256];

    float m = -1e30f, s = 0.f;
    for (int j = t; j < nv; j += 256) {
        float v = row[j];
        if (v > m) { s = s * __expf(m - v) + 1.f; m = v; }
        else s += __expf(v - m);
    }
    redm[t] = m; reds[t] = s;
    __syncthreads();
    for (int st = 128; st > 0; st >>= 1) {
        if (t < st) {
            float m2 = redm[t + st], s2 = reds[t + st];
            float m1 = redm[t], s1 = reds[t];
            float M = fmaxf(m1, m2);
            redm[t] = M;
            reds[t] = s1 * __expf(m1 - M) + s2 * __expf(m2 - M);
        }
        __syncthreads();
    }
    m = redm[0];
    float inv = 1.f / reds[0];

    for (int j = t; j < nv; j += 256) {
        float v = __expf(row[j] - m) * inv;
        bf16 h = __float2bfloat16(v);
        ah[j] = h;
        al[j] = __float2bfloat16(v - __bfloat162float(h));
    }
    bf16 zz = __float2bfloat16(0.f);
    for (int j = nv + t; j < Nn; j += 256) { ah[j] = zz; al[j] = zz; }
}

// ---------------- launch ----------------------------------------------------
static cudaStream_t make_stream() {
    cudaStream_t s;
    cudaStreamCreateWithFlags(&s, cudaStreamNonBlocking);
    return s;
}
static cudaEvent_t make_event() {
    cudaEvent_t e;
    cudaEventCreateWithFlags(&e, cudaEventDisableTiming);
    return e;
}

extern "C" void kernel_launch(void* const* d_in, const int* in_sizes, int n_in,
                              void* d_out, int out_size) {
    const float* X   = (const float*)d_in[0];
    const float* W_Q = (const float*)d_in[1];
    const float* W_K = (const float*)d_in[2];
    const float* W_V = (const float*)d_in[3];
    const float* W_O = (const float*)d_in[4];
    float* out = (float*)d_out;

    bf16 *Xhi, *Xlo, *XThi, *XTlo, *WQhi, *WQlo, *WKhi, *WKlo;
    bf16 *WOThi, *WOTlo, *WVThi, *WVTlo, *qhi, *qlo, *khi, *klo;
    bf16 *Mhi, *Mlo, *Ahi, *Alo, *cthi, *ctlo;
    float* L;
    cudaGetSymbolAddress((void**)&Xhi, g_Xhi);     cudaGetSymbolAddress((void**)&Xlo, g_Xlo);
    cudaGetSymbolAddress((void**)&XThi, g_XThi);   cudaGetSymbolAddress((void**)&XTlo, g_XTlo);
    cudaGetSymbolAddress((void**)&WQhi, g_WQhi);   cudaGetSymbolAddress((void**)&WQlo, g_WQlo);
    cudaGetSymbolAddress((void**)&WKhi, g_WKhi);   cudaGetSymbolAddress((void**)&WKlo, g_WKlo);
    cudaGetSymbolAddress((void**)&WOThi, g_WOThi); cudaGetSymbolAddress((void**)&WOTlo, g_WOTlo);
    cudaGetSymbolAddress((void**)&WVThi, g_WVThi); cudaGetSymbolAddress((void**)&WVTlo, g_WVTlo);
    cudaGetSymbolAddress((void**)&qhi, g_qhi);     cudaGetSymbolAddress((void**)&qlo, g_qlo);
    cudaGetSymbolAddress((void**)&khi, g_khi);     cudaGetSymbolAddress((void**)&klo, g_klo);
    cudaGetSymbolAddress((void**)&Mhi, g_Mhi);     cudaGetSymbolAddress((void**)&Mlo, g_Mlo);
    cudaGetSymbolAddress((void**)&Ahi, g_Ahi);     cudaGetSymbolAddress((void**)&Alo, g_Alo);
    cudaGetSymbolAddress((void**)&cthi, g_cthi);   cudaGetSymbolAddress((void**)&ctlo, g_ctlo);
    cudaGetSymbolAddress((void**)&L, g_L);

    cudaFuncSetAttribute(hgemm, cudaFuncAttributeMaxDynamicSharedMemorySize, GSMEM);

    static cudaStream_t s1 = make_stream();   // weights/M' + H-half branch
    static cudaStream_t s2 = make_stream();   // W_K convert + k-projection branch
    static cudaEvent_t evRoot = make_event(); // capture fork point
    static cudaEvent_t evX  = make_event();   // X conversion done
    static cudaEvent_t evK  = make_event();   // k-projection done
    static cudaEvent_t evLH = make_event();   // logits-H done
    static cudaEvent_t evM  = make_event();   // M' done
    static cudaEvent_t evOH = make_event();   // out-H done

    const long long sX  = (long long)DDIM * NSEQ;
    const long long sXT = (long long)NSEQ * DDIM;
    const long long sQ  = (long long)NSEQ * KDIM;
    const long long sL  = (long long)NSEQ * NSEQ;
    const int HALF = NSEQ / 2;

    dim3 tb(32, 8);
    cudaEventRecord(evRoot, 0);
    cudaStreamWaitEvent(s1, evRoot, 0);
    cudaStreamWaitEvent(s2, evRoot, 0);

    // s1: W_O/W_V transposes -> M'
    transpose_hl<<<dim3(DDIM / 32, KDIM / 32, 1), tb, 0, s1>>>(W_O, WOThi, WOTlo, KDIM, DDIM, 0, 0);
    transpose_hl<<<dim3(DDIM / 32, KDIM / 32, 1), tb, 0, s1>>>(W_V, WVThi, WVTlo, KDIM, DDIM, 0, 0);
    hgemm<<<dim3(DDIM / TN, DDIM / TM, 1), 256, GSMEM, s1>>>(
        WOThi, WOTlo, WVThi, WVTlo, nullptr, Mhi, Mlo, nullptr,
        DDIM, DDIM, KDIM, KDIM, KDIM, 0, 0, 0, 0, 0, 0, 0, 0);
    cudaEventRecord(evM, s1);

    // s2: W_K convert
    convert_hl<<<(KDIM * DDIM / 4) / 256, 256, 0, s2>>>(W_K, WKhi, WKlo, (long long)KDIM * DDIM);

    // s0: X conversion + W_Q convert
    convtrans_X<<<dim3(NSEQ / 32, DDIM / 32, BATCH), tb>>>(X, Xhi, Xlo, XThi, XTlo);
    cudaEventRecord(evX, 0);
    convert_hl<<<(KDIM * DDIM / 4) / 256, 256>>>(W_Q, WQhi, WQlo, (long long)KDIM * DDIM);

    // s2: k-projection
    cudaStreamWaitEvent(s2, evX, 0);
    hgemm<<<dim3(KDIM / TN, NSEQ / TM, BATCH), 256, GSMEM, s2>>>(
        XThi, XTlo, WKhi, WKlo, nullptr, khi, klo, nullptr,
        NSEQ, KDIM, DDIM, DDIM, DDIM, sXT, 0, sQ, 0, 0, 0, 0, 0);
    cudaEventRecord(evK, s2);

    // s0: q-projection
    hgemm<<<dim3(KDIM / TN, NSEQ / TM, BATCH), 256, GSMEM>>>(
        XThi, XTlo, WQhi, WQlo, nullptr, qhi, qlo, nullptr,
        NSEQ, KDIM, DDIM, DDIM, DDIM, sXT, 0, sQ, 0, 0, 0, 0, 0);

    cudaStreamWaitEvent(0, evK, 0);

    // logits-H: rows [1024,2048)
    hgemm<<<dim3(NSEQ / TN, HALF / TM, BATCH), 256, GSMEM>>>(
        qhi, qlo, khi, klo, L, nullptr, nullptr, nullptr,
        NSEQ, NSEQ, KDIM, KDIM, KDIM, sQ, sQ, sL, 0, 1, 0, HALF, 0);
    cudaEventRecord(evLH, 0);

    // logits-L: rows [0,1024)
    hgemm<<<dim3(NSEQ / TN, HALF / TM, BATCH), 256, GSMEM>>>(
        qhi, qlo, khi, klo, L, nullptr, nullptr, nullptr,
        NSEQ, NSEQ, KDIM, KDIM, KDIM, sQ, sQ, sL, 0, 1, 0, 0, 0);

    // s1 branch: softmax-H -> ctx-H -> out-H
    cudaStreamWaitEvent(s1, evLH, 0);
    softmax_rows<<<dim3(HALF, BATCH), 256, 0, s1>>>(L, Ahi, Alo, NSEQ, HALF);
    hgemm<<<dim3(DDIM / TN, HALF / TM, BATCH), 256, GSMEM, s1>>>(
        Ahi, Alo, Xhi, Xlo, nullptr, cthi, ctlo, nullptr,
        NSEQ, DDIM, NSEQ, NSEQ, NSEQ, sL, sX, sXT, 0, 0, 1, HALF, 0);
    hgemm<<<dim3(HALF / TN, DDIM / TM, BATCH), 256, GSMEM, s1>>>(
        Mhi, Mlo, cthi, ctlo, out, nullptr, nullptr, X,
        DDIM, NSEQ, DDIM, DDIM, DDIM, 0, sXT, sX, sX, 0, 0, 0, HALF);
    cudaEventRecord(evOH, s1);

    // s0: softmax-L -> ctx-L -> out-L
    softmax_rows<<<dim3(HALF, BATCH), 256>>>(L, Ahi, Alo, NSEQ, 0);
    hgemm<<<dim3(DDIM / TN, HALF / TM, BATCH), 256, GSMEM>>>(
        Ahi, Alo, Xhi, Xlo, nullptr, cthi, ctlo, nullptr,
        NSEQ, DDIM, NSEQ, NSEQ, NSEQ, sL, sX, sXT, 0, 0, 1, 0, 0);
    cudaStreamWaitEvent(0, evM, 0);
    hgemm<<<dim3(HALF / TN, DDIM / TM, BATCH), 256, GSMEM>>>(
        Mhi, Mlo, cthi, ctlo, out, nullptr, nullptr, X,
        DDIM, NSEQ, DDIM, DDIM, DDIM, 0, sXT, sX, sX, 0, 0, 0, 0);

    cudaStreamWaitEvent(0, evOH, 0);
}

// round 15
// speedup vs baseline: 1.0677x; 1.0677x over previous
#include <cuda_runtime.h>
#include <cuda_bf16.h>
#include <cstdint>

#define BATCH 4
#define DDIM  1024
#define NSEQ  2048
#define KDIM  1024

typedef __nv_bfloat16 bf16;

// ---------------- scratch (device globals; zero-init bss) -------------------
__device__ bf16 g_Xhi [BATCH * DDIM * NSEQ], g_Xlo [BATCH * DDIM * NSEQ];   // (b,d,n)
__device__ bf16 g_XThi[BATCH * NSEQ * DDIM], g_XTlo[BATCH * NSEQ * DDIM];   // (b,i,d)
__device__ bf16 g_WQhi[KDIM * DDIM], g_WQlo[KDIM * DDIM];                   // (k,d)
__device__ bf16 g_WKhi[KDIM * DDIM], g_WKlo[KDIM * DDIM];
__device__ bf16 g_WOThi[DDIM * KDIM], g_WOTlo[DDIM * KDIM];                 // (d,k)
__device__ bf16 g_WVThi[DDIM * KDIM], g_WVTlo[DDIM * KDIM];                 // (e,k)
__device__ bf16 g_qhi [BATCH * NSEQ * KDIM], g_qlo [BATCH * NSEQ * KDIM];   // (b,i,k)
__device__ bf16 g_khi [BATCH * NSEQ * KDIM], g_klo [BATCH * NSEQ * KDIM];   // (b,j,k)
__device__ bf16 g_Mhi [DDIM * DDIM], g_Mlo [DDIM * DDIM];                   // M'(d,e)
__device__ bf16 g_Yhi [BATCH * DDIM * NSEQ], g_Ylo [BATCH * DDIM * NSEQ];   // Y=M'X (b,d,t)
__device__ float g_L  [BATCH * NSEQ * NSEQ];                                // logits fp32
__device__ bf16 g_Ahi [BATCH * NSEQ * NSEQ], g_Alo [BATCH * NSEQ * NSEQ];   // softmax out

// ---------------- helpers ----------------------------------------------------
__device__ __forceinline__ uint32_t smem_u32(const void* p) {
    uint32_t a;
    asm("{ .reg .u64 t; cvta.to.shared.u64 t, %1; cvt.u32.u64 %0, t; }" : "=r"(a) : "l"(p));
    return a;
}
__device__ __forceinline__ void ldsm4(uint32_t* r, uint32_t addr) {
    asm volatile("ldmatrix.sync.aligned.m8n8.x4.shared.b16 {%0,%1,%2,%3}, [%4];"
                 : "=r"(r[0]), "=r"(r[1]), "=r"(r[2]), "=r"(r[3]) : "r"(addr));
}
__device__ __forceinline__ void mma16816(float* d, const uint32_t* a, const uint32_t* b) {
    asm volatile(
        "mma.sync.aligned.m16n8k16.row.col.f32.bf16.bf16.f32 "
        "{%0,%1,%2,%3}, {%4,%5,%6,%7}, {%8,%9}, {%0,%1,%2,%3};"
        : "+f"(d[0]), "+f"(d[1]), "+f"(d[2]), "+f"(d[3])
        : "r"(a[0]), "r"(a[1]), "r"(a[2]), "r"(a[3]), "r"(b[0]), "r"(b[1]));
}
__device__ __forceinline__ void cpasync16(uint32_t dst, const void* src) {
    asm volatile("cp.async.cg.shared.global [%0], [%1], 16;" :: "r"(dst), "l"(src));
}
__device__ __forceinline__ void cp_commit() { asm volatile("cp.async.commit_group;"); }
__device__ __forceinline__ void cp_wait1()  { asm volatile("cp.async.wait_group 1;"); }

__device__ __forceinline__ uint32_t pack_hi(float a, float b) {
    bf16 h0 = __float2bfloat16(a), h1 = __float2bfloat16(b);
    return (uint32_t)__bfloat16_as_ushort(h0) | ((uint32_t)__bfloat16_as_ushort(h1) << 16);
}
__device__ __forceinline__ uint32_t pack_lo(float a, float b) {
    bf16 h0 = __float2bfloat16(a), h1 = __float2bfloat16(b);
    float l0 = a - __bfloat162float(h0), l1 = b - __bfloat162float(h1);
    return (uint32_t)__bfloat16_as_ushort(__float2bfloat16(l0)) |
           ((uint32_t)__bfloat16_as_ushort(__float2bfloat16(l1)) << 16);
}

// ---------------- convert fp32 -> bf16 hi/lo --------------------------------
__global__ void convert_hl(const float* __restrict__ in, bf16* __restrict__ hi,
                           bf16* __restrict__ lo, long long n) {
    long long i = ((long long)blockIdx.x * blockDim.x + threadIdx.x) * 4;
    if (i >= n) return;
    float4 v = *(const float4*)(in + i);
    *(uint2*)(hi + i) = make_uint2(pack_hi(v.x, v.y), pack_hi(v.z, v.w));
    *(uint2*)(lo + i) = make_uint2(pack_lo(v.x, v.y), pack_lo(v.z, v.w));
}

// ---------------- transpose fp32 -> bf16 hi/lo ------------------------------
__global__ void transpose_hl(const float* __restrict__ in, bf16* __restrict__ hi,
                             bf16* __restrict__ lo, int rows, int cols,
                             long long sIn, long long sOut) {
    __shared__ float tile[32][33];
    const float* I = in + (long long)blockIdx.z * sIn;
    int r0 = blockIdx.y * 32, c0 = blockIdx.x * 32;
    int x = threadIdx.x, y = threadIdx.y;
#pragma unroll
    for (int j = y; j < 32; j += 8)
        tile[j][x] = I[(long long)(r0 + j) * cols + c0 + x];
    __syncthreads();
    long long zo = (long long)blockIdx.z * sOut;
#pragma unroll
    for (int j = y; j < 32; j += 8) {
        float v = tile[x][j];
        long long o = zo + (long long)(c0 + j) * rows + r0 + x;
        bf16 h = __float2bfloat16(v);
        hi[o] = h;
        lo[o] = __float2bfloat16(v - __bfloat162float(h));
    }
}

// ---------------- fused X: convert + transpose, vectorized u32 stores -------
__global__ void convtrans_X(const float* __restrict__ in,
                            bf16* __restrict__ hi, bf16* __restrict__ lo,
                            bf16* __restrict__ thi, bf16* __restrict__ tlo) {
    __shared__ float tile[32][33];
    long long zb = (long long)blockIdx.z * DDIM * NSEQ;
    int r0 = blockIdx.y * 32, c0 = blockIdx.x * 32;
    int tid = threadIdx.y * 32 + threadIdx.x;
    int l = tid & 15, g = tid >> 4;
#pragma unroll
    for (int it = 0; it < 2; ++it) {
        int j = g + it * 16;
        long long o = zb + (long long)(r0 + j) * NSEQ + c0 + 2 * l;
        float2 v = *(const float2*)(in + o);
        tile[j][2 * l]     = v.x;
        tile[j][2 * l + 1] = v.y;
        *(uint32_t*)(hi + o) = pack_hi(v.x, v.y);
        *(uint32_t*)(lo + o) = pack_lo(v.x, v.y);
    }
    __syncthreads();
#pragma unroll
    for (int it = 0; it < 2; ++it) {
        int j = g + it * 16;
        float a = tile[2 * l][j], b2 = tile[2 * l + 1][j];
        long long o = zb + (long long)(c0 + j) * DDIM + r0 + 2 * l;
        *(uint32_t*)(thi + o) = pack_hi(a, b2);
        *(uint32_t*)(tlo + o) = pack_lo(a, b2);
    }
}

// ---------------- bf16 hi/lo HMMA NT GEMM -----------------------------------
// C[m][n] = sum_k A[m][k]*B[n][k]; A rows ld=ldA, B rows ld=ldB.
// kcap: 0 none; 1 cap k at m0+TM (A rows causal-zero); 2 cap k at n0+TN
// (B rows causal-zero, e.g. A-matrix operand of the out GEMM).
#define TM 128
#define TN 128
#define KC 32
#define TILE_B 8192
#define STAGE_B (4 * TILE_B)
#define STAGES 3
#define GSMEM (STAGES * STAGE_B)

__global__ void __launch_bounds__(256, 2)
hgemm(const bf16* __restrict__ Ahi_, const bf16* __restrict__ Alo_,
      const bf16* __restrict__ Bhi_, const bf16* __restrict__ Blo_,
      float* __restrict__ Cf, bf16* __restrict__ Chi, bf16* __restrict__ Clo,
      const float* __restrict__ Res,
      int M, int N, int Kk, int ldA, int ldB,
      long long sA, long long sB, long long sC, long long sRes,
      int causal, int kcap, int m_off, int n_off) {
    int bx = (kcap == 2) ? (gridDim.x - 1 - blockIdx.x) : blockIdx.x;
    int by = (causal || kcap == 1) ? (gridDim.y - 1 - blockIdx.y) : blockIdx.y;
    int m0 = m_off + by * TM;
    int n0 = n_off + bx * TN;
    if (causal && n0 > m0 + TM - 1) return;

    extern __shared__ char sm[];
    uint32_t sb = smem_u32(sm);
    int tid = threadIdx.x, lane = tid & 31, wid = tid >> 5;
    int wm = wid & 1, wn = wid >> 1;
    long long z = blockIdx.z;

    int row = tid >> 1, seg0 = (tid & 1) * 2;
    int ssw = (row >> 1) & 3;
    uint32_t so0 = (uint32_t)(row * 64 + ((seg0 ^ ssw) << 4));
    uint32_t so1 = (uint32_t)(row * 64 + (((seg0 + 1) ^ ssw) << 4));
    const bf16* pAhi = Ahi_ + z * sA + (long long)(m0 + row) * ldA + seg0 * 8;
    const bf16* pAlo = Alo_ + z * sA + (long long)(m0 + row) * ldA + seg0 * 8;
    const bf16* pBhi = Bhi_ + z * sB + (long long)(n0 + row) * ldB + seg0 * 8;
    const bf16* pBlo = Blo_ + z * sB + (long long)(n0 + row) * ldB + seg0 * 8;

    int ra = wm * 64 + (lane & 15);
    int abit = lane >> 4;
    uint32_t aRow = (uint32_t)ra * 64;
    int swA = (ra >> 1) & 3;
    uint32_t colA[2] = { (uint32_t)(((0 + abit) ^ swA) << 4),
                         (uint32_t)(((2 + abit) ^ swA) << 4) };
    int rb = wn * 32 + ((lane >> 4) << 3) + (lane & 7);
    int bbit = (lane >> 3) & 1;
    uint32_t bRow = (uint32_t)rb * 64;
    int swB = (rb >> 1) & 3;
    uint32_t colB[2] = { (uint32_t)(((0 + bbit) ^ swB) << 4),
                         (uint32_t)(((2 + bbit) ^ swB) << 4) };

    float acc[4][4][4];
#pragma unroll
    for (int mt = 0; mt < 4; ++mt)
#pragma unroll
        for (int nt = 0; nt < 4; ++nt)
#pragma unroll
            for (int r = 0; r < 4; ++r) acc[mt][nt][r] = 0.f;

    int KkE = Kk;
    if (kcap == 1) KkE = (m0 + TM < Kk) ? m0 + TM : Kk;
    else if (kcap == 2) KkE = (n0 + TN < Kk) ? n0 + TN : Kk;
    const int nc = KkE / KC;

#pragma unroll
    for (int s = 0; s < STAGES - 1; ++s) {
        long long off = (long long)s * KC;
        uint32_t d = sb + s * STAGE_B;
        cpasync16(d + 0 * TILE_B + so0, pAhi + off);
        cpasync16(d + 0 * TILE_B + so1, pAhi + off + 8);
        cpasync16(d + 1 * TILE_B + so0, pAlo + off);
        cpasync16(d + 1 * TILE_B + so1, pAlo + off + 8);
        cpasync16(d + 2 * TILE_B + so0, pBhi + off);
        cpasync16(d + 2 * TILE_B + so1, pBhi + off + 8);
        cpasync16(d + 3 * TILE_B + so0, pBlo + off);
        cpasync16(d + 3 * TILE_B + so1, pBlo + off + 8);
        cp_commit();
    }

    for (int c = 0; c < nc; ++c) {
        cp_wait1();
        __syncthreads();
        if (c + 2 < nc) {
            int st = (c + 2) % STAGES;
            long long off = (long long)(c + 2) * KC;
            uint32_t d = sb + st * STAGE_B;
            cpasync16(d + 0 * TILE_B + so0, pAhi + off);
            cpasync16(d + 0 * TILE_B + so1, pAhi + off + 8);
            cpasync16(d + 1 * TILE_B + so0, pAlo + off);
            cpasync16(d + 1 * TILE_B + so1, pAlo + off + 8);
            cpasync16(d + 2 * TILE_B + so0, pBhi + off);
            cpasync16(d + 2 * TILE_B + so1, pBhi + off + 8);
            cpasync16(d + 3 * TILE_B + so0, pBlo + off);
            cpasync16(d + 3 * TILE_B + so1, pBlo + off + 8);
            cp_commit();
        } else {
            cp_commit();
        }

        uint32_t bA = sb + (c % STAGES) * STAGE_B;
        uint32_t bAhi = bA, bAlo = bA + TILE_B, bBhi = bA + 2 * TILE_B, bBlo = bA + 3 * TILE_B;

#pragma unroll
        for (int kk2 = 0; kk2 < 2; ++kk2) {
            uint32_t ah[4][4], bh[4][2], bl[4][2];
#pragma unroll
            for (int mt = 0; mt < 4; ++mt)
                ldsm4(ah[mt], bAhi + aRow + mt * 1024 + colA[kk2]);
#pragma unroll
            for (int jp = 0; jp < 2; ++jp) {
                uint32_t r[4];
                ldsm4(r, bBhi + bRow + jp * 1024 + colB[kk2]);
                bh[2 * jp][0] = r[0]; bh[2 * jp][1] = r[1];
                bh[2 * jp + 1][0] = r[2]; bh[2 * jp + 1][1] = r[3];
            }
#pragma unroll
            for (int jp = 0; jp < 2; ++jp) {
                uint32_t r[4];
                ldsm4(r, bBlo + bRow + jp * 1024 + colB[kk2]);
                bl[2 * jp][0] = r[0]; bl[2 * jp][1] = r[1];
                bl[2 * jp + 1][0] = r[2]; bl[2 * jp + 1][1] = r[3];
            }
#pragma unroll
            for (int mt = 0; mt < 4; ++mt)
#pragma unroll
                for (int nt = 0; nt < 4; ++nt)
                    mma16816(acc[mt][nt], ah[mt], bh[nt]);

            uint32_t al[4][4];
#pragma unroll
            for (int mt = 0; mt < 4; ++mt)
                ldsm4(al[mt], bAlo + aRow + mt * 1024 + colA[kk2]);
#pragma unroll
            for (int mt = 0; mt < 4; ++mt)
#pragma unroll
                for (int nt = 0; nt < 4; ++nt)
                    mma16816(acc[mt][nt], ah[mt], bl[nt]);
#pragma unroll
            for (int mt = 0; mt < 4; ++mt)
#pragma unroll
                for (int nt = 0; nt < 4; ++nt)
                    mma16816(acc[mt][nt], al[mt], bh[nt]);
        }
    }

    int er = lane >> 2, ec = (lane & 3) * 2;
    if (Cf) {
        float* Cb = Cf + z * sC;
        const float* Rb = Res ? Res + z * sRes : nullptr;
#pragma unroll
        for (int mt = 0; mt < 4; ++mt) {
#pragma unroll
            for (int nt = 0; nt < 4; ++nt) {
                long long r0 = (long long)(m0 + wm * 64 + mt * 16 + er);
                int col = n0 + wn * 32 + nt * 8 + ec;
                float2 v0 = make_float2(acc[mt][nt][0], acc[mt][nt][1]);
                float2 v1 = make_float2(acc[mt][nt][2], acc[mt][nt][3]);
                if (Rb) {
                    float2 q0 = *(const float2*)(Rb + r0 * N + col);
                    float2 q1 = *(const float2*)(Rb + (r0 + 8) * N + col);
                    v0.x += q0.x; v0.y += q0.y; v1.x += q1.x; v1.y += q1.y;
                }
                *(float2*)(Cb + r0 * N + col)       = v0;
                *(float2*)(Cb + (r0 + 8) * N + col) = v1;
            }
        }
    } else {
        bf16* Hb = Chi + z * sC;
        bf16* Lb = Clo + z * sC;
#pragma unroll
        for (int mt = 0; mt < 4; ++mt) {
#pragma unroll
            for (int nt = 0; nt < 4; ++nt) {
                long long r0 = (long long)(m0 + wm * 64 + mt * 16 + er);
                int col = n0 + wn * 32 + nt * 8 + ec;
#pragma unroll
                for (int h = 0; h < 2; ++h) {
                    float v0 = acc[mt][nt][2 * h], v1 = acc[mt][nt][2 * h + 1];
                    long long o = (r0 + 8 * h) * N + col;
                    *(uint32_t*)(Hb + o) = pack_hi(v0, v1);
                    *(uint32_t*)(Lb + o) = pack_lo(v0, v1);
                }
            }
        }
    }
}

// ---------------- row softmax: online max+sum (2 passes), causal ------------
__global__ void softmax_rows(const float* __restrict__ L, bf16* __restrict__ Ahi,
                             bf16* __restrict__ Alo, int Nn, int i_off) {
    int b = blockIdx.y, i = i_off + blockIdx.x;
    const float* row = L + ((long long)b * Nn + i) * Nn;
    bf16* ah = Ahi + ((long long)b * Nn + i) * Nn;
    bf16* al = Alo + ((long long)b * Nn + i) * Nn;
    int nv = i + 1;
    int t = threadIdx.x;
    __shared__ float redm[256], reds[256];

    float m = -1e30f, s = 0.f;
    for (int j = t; j < nv; j += 256) {
        float v = row[j];
        if (v > m) { s = s * __expf(m - v) + 1.f; m = v; }
        else s += __expf(v - m);
    }
    redm[t] = m; reds[t] = s;
    __syncthreads();
    for (int st = 128; st > 0; st >>= 1) {
        if (t < st) {
            float m2 = redm[t + st], s2 = reds[t + st];
            float m1 = redm[t], s1 = reds[t];
            float M = fmaxf(m1, m2);
            redm[t] = M;
            reds[t] = s1 * __expf(m1 - M) + s2 * __expf(m2 - M);
        }
        __syncthreads();
    }
    m = redm[0];
    float inv = 1.f / reds[0];

    for (int j = t; j < nv; j += 256) {
        float v = __expf(row[j] - m) * inv;
        bf16 h = __float2bfloat16(v);
        ah[j] = h;
        al[j] = __float2bfloat16(v - __bfloat162float(h));
    }
    bf16 zz = __float2bfloat16(0.f);
    for (int j = nv + t; j < Nn; j += 256) { ah[j] = zz; al[j] = zz; }
}

// ---------------- launch ----------------------------------------------------
static cudaStream_t make_stream() {
    cudaStream_t s;
    cudaStreamCreateWithFlags(&s, cudaStreamNonBlocking);
    return s;
}
static cudaEvent_t make_event() {
    cudaEvent_t e;
    cudaEventCreateWithFlags(&e, cudaEventDisableTiming);
    return e;
}

extern "C" void kernel_launch(void* const* d_in, const int* in_sizes, int n_in,
                              void* d_out, int out_size) {
    const float* X   = (const float*)d_in[0];
    const float* W_Q = (const float*)d_in[1];
    const float* W_K = (const float*)d_in[2];
    const float* W_V = (const float*)d_in[3];
    const float* W_O = (const float*)d_in[4];
    float* out = (float*)d_out;

    bf16 *Xhi, *Xlo, *XThi, *XTlo, *WQhi, *WQlo, *WKhi, *WKlo;
    bf16 *WOThi, *WOTlo, *WVThi, *WVTlo, *qhi, *qlo, *khi, *klo;
    bf16 *Mhi, *Mlo, *Yhi, *Ylo, *Ahi, *Alo;
    float* L;
    cudaGetSymbolAddress((void**)&Xhi, g_Xhi);     cudaGetSymbolAddress((void**)&Xlo, g_Xlo);
    cudaGetSymbolAddress((void**)&XThi, g_XThi);   cudaGetSymbolAddress((void**)&XTlo, g_XTlo);
    cudaGetSymbolAddress((void**)&WQhi, g_WQhi);   cudaGetSymbolAddress((void**)&WQlo, g_WQlo);
    cudaGetSymbolAddress((void**)&WKhi, g_WKhi);   cudaGetSymbolAddress((void**)&WKlo, g_WKlo);
    cudaGetSymbolAddress((void**)&WOThi, g_WOThi); cudaGetSymbolAddress((void**)&WOTlo, g_WOTlo);
    cudaGetSymbolAddress((void**)&WVThi, g_WVThi); cudaGetSymbolAddress((void**)&WVTlo, g_WVTlo);
    cudaGetSymbolAddress((void**)&qhi, g_qhi);     cudaGetSymbolAddress((void**)&qlo, g_qlo);
    cudaGetSymbolAddress((void**)&khi, g_khi);     cudaGetSymbolAddress((void**)&klo, g_klo);
    cudaGetSymbolAddress((void**)&Mhi, g_Mhi);     cudaGetSymbolAddress((void**)&Mlo, g_Mlo);
    cudaGetSymbolAddress((void**)&Yhi, g_Yhi);     cudaGetSymbolAddress((void**)&Ylo, g_Ylo);
    cudaGetSymbolAddress((void**)&Ahi, g_Ahi);     cudaGetSymbolAddress((void**)&Alo, g_Alo);
    cudaGetSymbolAddress((void**)&L, g_L);

    cudaFuncSetAttribute(hgemm, cudaFuncAttributeMaxDynamicSharedMemorySize, GSMEM);

    static cudaStream_t s1 = make_stream();   // weights/M'/Y + H-half branch
    static cudaStream_t s2 = make_stream();   // W_K convert + k-projection branch
    static cudaEvent_t evRoot = make_event(); // capture fork point
    static cudaEvent_t evX  = make_event();   // X conversion done
    static cudaEvent_t evK  = make_event();   // k-projection done
    static cudaEvent_t evLH = make_event();   // logits-H done
    static cudaEvent_t evY  = make_event();   // Y = M'X done
    static cudaEvent_t evOH = make_event();   // out-H done

    const long long sX  = (long long)DDIM * NSEQ;
    const long long sXT = (long long)NSEQ * DDIM;
    const long long sQ  = (long long)NSEQ * KDIM;
    const long long sL  = (long long)NSEQ * NSEQ;
    const int HALF = NSEQ / 2;

    dim3 tb(32, 8);
    cudaEventRecord(evRoot, 0);
    cudaStreamWaitEvent(s1, evRoot, 0);
    cudaStreamWaitEvent(s2, evRoot, 0);

    // s1: W_O/W_V transposes -> M' -> Y = M'.X (pre-softmax; overlaps q/k/logits)
    transpose_hl<<<dim3(DDIM / 32, KDIM / 32, 1), tb, 0, s1>>>(W_O, WOThi, WOTlo, KDIM, DDIM, 0, 0);
    transpose_hl<<<dim3(DDIM / 32, KDIM / 32, 1), tb, 0, s1>>>(W_V, WVThi, WVTlo, KDIM, DDIM, 0, 0);
    hgemm<<<dim3(DDIM / TN, DDIM / TM, 1), 256, GSMEM, s1>>>(
        WOThi, WOTlo, WVThi, WVTlo, nullptr, Mhi, Mlo, nullptr,
        DDIM, DDIM, KDIM, KDIM, KDIM, 0, 0, 0, 0, 0, 0, 0, 0);

    // s2: W_K convert
    convert_hl<<<(KDIM * DDIM / 4) / 256, 256, 0, s2>>>(W_K, WKhi, WKlo, (long long)KDIM * DDIM);

    // s0: X conversion + W_Q convert
    convtrans_X<<<dim3(NSEQ / 32, DDIM / 32, BATCH), tb>>>(X, Xhi, Xlo, XThi, XTlo);
    cudaEventRecord(evX, 0);
    convert_hl<<<(KDIM * DDIM / 4) / 256, 256>>>(W_Q, WQhi, WQlo, (long long)KDIM * DDIM);

    // s1: Y[b][d][t] = sum_e M'[d][e] * XT[t][e]   (bf16 hi/lo out)
    cudaStreamWaitEvent(s1, evX, 0);
    hgemm<<<dim3(NSEQ / TN, DDIM / TM, BATCH), 256, GSMEM, s1>>>(
        Mhi, Mlo, XThi, XTlo, nullptr, Yhi, Ylo, nullptr,
        DDIM, NSEQ, DDIM, DDIM, DDIM, 0, sXT, sX, 0, 0, 0, 0, 0);
    cudaEventRecord(evY, s1);

    // s2: k-projection
    cudaStreamWaitEvent(s2, evX, 0);
    hgemm<<<dim3(KDIM / TN, NSEQ / TM, BATCH), 256, GSMEM, s2>>>(
        XThi, XTlo, WKhi, WKlo, nullptr, khi, klo, nullptr,
        NSEQ, KDIM, DDIM, DDIM, DDIM, sXT, 0, sQ, 0, 0, 0, 0, 0);
    cudaEventRecord(evK, s2);

    // s0: q-projection
    hgemm<<<dim3(KDIM / TN, NSEQ / TM, BATCH), 256, GSMEM>>>(
        XThi, XTlo, WQhi, WQlo, nullptr, qhi, qlo, nullptr,
        NSEQ, KDIM, DDIM, DDIM, DDIM, sXT, 0, sQ, 0, 0, 0, 0, 0);

    cudaStreamWaitEvent(0, evK, 0);

    // logits-H: rows [1024,2048)
    hgemm<<<dim3(NSEQ / TN, HALF / TM, BATCH), 256, GSMEM>>>(
        qhi, qlo, khi, klo, L, nullptr, nullptr, nullptr,
        NSEQ, NSEQ, KDIM, KDIM, KDIM, sQ, sQ, sL, 0, 1, 0, HALF, 0);
    cudaEventRecord(evLH, 0);

    // logits-L: rows [0,1024)
    hgemm<<<dim3(NSEQ / TN, HALF / TM, BATCH), 256, GSMEM>>>(
        qhi, qlo, khi, klo, L, nullptr, nullptr, nullptr,
        NSEQ, NSEQ, KDIM, KDIM, KDIM, sQ, sQ, sL, 0, 1, 0, 0, 0);

    // s1 branch: softmax-H -> out-H (Y already ordered on s1)
    cudaStreamWaitEvent(s1, evLH, 0);
    softmax_rows<<<dim3(HALF, BATCH), 256, 0, s1>>>(L, Ahi, Alo, NSEQ, HALF);
    // out[d][i] = X[d][i] + sum_t Y[d][t] A[i][t], i in [1024,2048), k capped at n0+TN
    hgemm<<<dim3(HALF / TN, DDIM / TM, BATCH), 256, GSMEM, s1>>>(
        Yhi, Ylo, Ahi, Alo, out, nullptr, nullptr, X,
        DDIM, NSEQ, NSEQ, NSEQ, NSEQ, sX, sL, sX, sX, 0, 2, 0, HALF);
    cudaEventRecord(evOH, s1);

    // s0: softmax-L -> out-L
    softmax_rows<<<dim3(HALF, BATCH), 256>>>(L, Ahi, Alo, NSEQ, 0);
    cudaStreamWaitEvent(0, evY, 0);
    hgemm<<<dim3(HALF / TN, DDIM / TM, BATCH), 256, GSMEM>>>(
        Yhi, Ylo, Ahi, Alo, out, nullptr, nullptr, X,
        DDIM, NSEQ, NSEQ, NSEQ, NSEQ, sX, sL, sX, sX, 0, 2, 0, 0);

    cudaStreamWaitEvent(0, evOH, 0);
}

// round 17
// speedup vs baseline: 1.1009x; 1.0311x over previous
#include <cuda_runtime.h>
#include <cuda_bf16.h>
#include <cstdint>

#define BATCH 4
#define DDIM  1024
#define NSEQ  2048
#define KDIM  1024

typedef __nv_bfloat16 bf16;

// ---------------- scratch (device globals; zero-init bss) -------------------
__device__ bf16 g_Xhi [BATCH * DDIM * NSEQ], g_Xlo [BATCH * DDIM * NSEQ];   // (b,d,n)
__device__ bf16 g_XThi[BATCH * NSEQ * DDIM], g_XTlo[BATCH * NSEQ * DDIM];   // (b,i,d)
__device__ bf16 g_WQhi[KDIM * DDIM], g_WQlo[KDIM * DDIM];                   // (k,d)
__device__ bf16 g_WKhi[KDIM * DDIM], g_WKlo[KDIM * DDIM];
__device__ bf16 g_WOThi[DDIM * KDIM], g_WOTlo[DDIM * KDIM];                 // (d,k)
__device__ bf16 g_WVThi[DDIM * KDIM], g_WVTlo[DDIM * KDIM];                 // (e,k)
__device__ bf16 g_qhi [BATCH * NSEQ * KDIM], g_qlo [BATCH * NSEQ * KDIM];   // (b,i,k)
__device__ bf16 g_khi [BATCH * NSEQ * KDIM], g_klo [BATCH * NSEQ * KDIM];   // (b,j,k)
__device__ bf16 g_Mhi [DDIM * DDIM], g_Mlo [DDIM * DDIM];                   // M'(d,e)
__device__ bf16 g_Yhi [BATCH * DDIM * NSEQ], g_Ylo [BATCH * DDIM * NSEQ];   // Y=M'X (b,d,t)
__device__ float g_L  [BATCH * NSEQ * NSEQ];                                // logits fp32
__device__ bf16 g_Ahi [BATCH * NSEQ * NSEQ], g_Alo [BATCH * NSEQ * NSEQ];   // softmax out

// ---------------- helpers ----------------------------------------------------
__device__ __forceinline__ uint32_t smem_u32(const void* p) {
    uint32_t a;
    asm("{ .reg .u64 t; cvta.to.shared.u64 t, %1; cvt.u32.u64 %0, t; }" : "=r"(a) : "l"(p));
    return a;
}
__device__ __forceinline__ void ldsm4(uint32_t* r, uint32_t addr) {
    asm volatile("ldmatrix.sync.aligned.m8n8.x4.shared.b16 {%0,%1,%2,%3}, [%4];"
                 : "=r"(r[0]), "=r"(r[1]), "=r"(r[2]), "=r"(r[3]) : "r"(addr));
}
__device__ __forceinline__ void mma16816(float* d, const uint32_t* a, const uint32_t* b) {
    asm volatile(
        "mma.sync.aligned.m16n8k16.row.col.f32.bf16.bf16.f32 "
        "{%0,%1,%2,%3}, {%4,%5,%6,%7}, {%8,%9}, {%0,%1,%2,%3};"
        : "+f"(d[0]), "+f"(d[1]), "+f"(d[2]), "+f"(d[3])
        : "r"(a[0]), "r"(a[1]), "r"(a[2]), "r"(a[3]), "r"(b[0]), "r"(b[1]));
}
__device__ __forceinline__ void cpasync16(uint32_t dst, const void* src) {
    asm volatile("cp.async.cg.shared.global [%0], [%1], 16;" :: "r"(dst), "l"(src));
}
__device__ __forceinline__ void cp_commit() { asm volatile("cp.async.commit_group;"); }
__device__ __forceinline__ void cp_wait1()  { asm volatile("cp.async.wait_group 1;"); }

__device__ __forceinline__ uint32_t pack_hi(float a, float b) {
    bf16 h0 = __float2bfloat16(a), h1 = __float2bfloat16(b);
    return (uint32_t)__bfloat16_as_ushort(h0) | ((uint32_t)__bfloat16_as_ushort(h1) << 16);
}
__device__ __forceinline__ uint32_t pack_lo(float a, float b) {
    bf16 h0 = __float2bfloat16(a), h1 = __float2bfloat16(b);
    float l0 = a - __bfloat162float(h0), l1 = b - __bfloat162float(h1);
    return (uint32_t)__bfloat16_as_ushort(__float2bfloat16(l0)) |
           ((uint32_t)__bfloat16_as_ushort(__float2bfloat16(l1)) << 16);
}

// ---------------- convert fp32 -> bf16 hi/lo --------------------------------
__global__ void convert_hl(const float* __restrict__ in, bf16* __restrict__ hi,
                           bf16* __restrict__ lo, long long n) {
    long long i = ((long long)blockIdx.x * blockDim.x + threadIdx.x) * 4;
    if (i >= n) return;
    float4 v = *(const float4*)(in + i);
    *(uint2*)(hi + i) = make_uint2(pack_hi(v.x, v.y), pack_hi(v.z, v.w));
    *(uint2*)(lo + i) = make_uint2(pack_lo(v.x, v.y), pack_lo(v.z, v.w));
}

// ---------------- transpose fp32 -> bf16 hi/lo ------------------------------
__global__ void transpose_hl(const float* __restrict__ in, bf16* __restrict__ hi,
                             bf16* __restrict__ lo, int rows, int cols,
                             long long sIn, long long sOut) {
    __shared__ float tile[32][33];
    const float* I = in + (long long)blockIdx.z * sIn;
    int r0 = blockIdx.y * 32, c0 = blockIdx.x * 32;
    int x = threadIdx.x, y = threadIdx.y;
#pragma unroll
    for (int j = y; j < 32; j += 8)
        tile[j][x] = I[(long long)(r0 + j) * cols + c0 + x];
    __syncthreads();
    long long zo = (long long)blockIdx.z * sOut;
#pragma unroll
    for (int j = y; j < 32; j += 8) {
        float v = tile[x][j];
        long long o = zo + (long long)(c0 + j) * rows + r0 + x;
        bf16 h = __float2bfloat16(v);
        hi[o] = h;
        lo[o] = __float2bfloat16(v - __bfloat162float(h));
    }
}

// ---------------- fused X: convert + transpose, vectorized u32 stores -------
__global__ void convtrans_X(const float* __restrict__ in,
                            bf16* __restrict__ hi, bf16* __restrict__ lo,
                            bf16* __restrict__ thi, bf16* __restrict__ tlo) {
    __shared__ float tile[32][33];
    long long zb = (long long)blockIdx.z * DDIM * NSEQ;
    int r0 = blockIdx.y * 32, c0 = blockIdx.x * 32;
    int tid = threadIdx.y * 32 + threadIdx.x;
    int l = tid & 15, g = tid >> 4;
#pragma unroll
    for (int it = 0; it < 2; ++it) {
        int j = g + it * 16;
        long long o = zb + (long long)(r0 + j) * NSEQ + c0 + 2 * l;
        float2 v = *(const float2*)(in + o);
        tile[j][2 * l]     = v.x;
        tile[j][2 * l + 1] = v.y;
        *(uint32_t*)(hi + o) = pack_hi(v.x, v.y);
        *(uint32_t*)(lo + o) = pack_lo(v.x, v.y);
    }
    __syncthreads();
#pragma unroll
    for (int it = 0; it < 2; ++it) {
        int j = g + it * 16;
        float a = tile[2 * l][j], b2 = tile[2 * l + 1][j];
        long long o = zb + (long long)(c0 + j) * DDIM + r0 + 2 * l;
        *(uint32_t*)(thi + o) = pack_hi(a, b2);
        *(uint32_t*)(tlo + o) = pack_lo(a, b2);
    }
}

// ---------------- bf16 hi/lo HMMA NT GEMM -----------------------------------
// C[m][n] = sum_k A[m][k]*B[n][k]; A rows ld=ldA, B rows ld=ldB.
// kcap: 0 none; 1 cap k at m0+TM (A rows causal-zero); 2 cap k at n0+TN.
#define TM 128
#define TN 128
#define KC 32
#define TILE_B 8192
#define STAGE_B (4 * TILE_B)
#define STAGES 3
#define GSMEM (STAGES * STAGE_B)

__global__ void __launch_bounds__(256, 2)
hgemm(const bf16* __restrict__ Ahi_, const bf16* __restrict__ Alo_,
      const bf16* __restrict__ Bhi_, const bf16* __restrict__ Blo_,
      float* __restrict__ Cf, bf16* __restrict__ Chi, bf16* __restrict__ Clo,
      const float* __restrict__ Res,
      int M, int N, int Kk, int ldA, int ldB,
      long long sA, long long sB, long long sC, long long sRes,
      int causal, int kcap, int m_off, int n_off) {
    int bx = (kcap == 2) ? (gridDim.x - 1 - blockIdx.x) : blockIdx.x;
    int by = (causal || kcap == 1) ? (gridDim.y - 1 - blockIdx.y) : blockIdx.y;
    int m0 = m_off + by * TM;
    int n0 = n_off + bx * TN;
    if (causal && n0 > m0 + TM - 1) return;

    extern __shared__ char sm[];
    uint32_t sb = smem_u32(sm);
    int tid = threadIdx.x, lane = tid & 31, wid = tid >> 5;
    int wm = wid & 1, wn = wid >> 1;
    long long z = blockIdx.z;

    int row = tid >> 1, seg0 = (tid & 1) * 2;
    int ssw = (row >> 1) & 3;
    uint32_t so0 = (uint32_t)(row * 64 + ((seg0 ^ ssw) << 4));
    uint32_t so1 = (uint32_t)(row * 64 + (((seg0 + 1) ^ ssw) << 4));
    const bf16* pAhi = Ahi_ + z * sA + (long long)(m0 + row) * ldA + seg0 * 8;
    const bf16* pAlo = Alo_ + z * sA + (long long)(m0 + row) * ldA + seg0 * 8;
    const bf16* pBhi = Bhi_ + z * sB + (long long)(n0 + row) * ldB + seg0 * 8;
    const bf16* pBlo = Blo_ + z * sB + (long long)(n0 + row) * ldB + seg0 * 8;

    int ra = wm * 64 + (lane & 15);
    int abit = lane >> 4;
    uint32_t aRow = (uint32_t)ra * 64;
    int swA = (ra >> 1) & 3;
    uint32_t colA[2] = { (uint32_t)(((0 + abit) ^ swA) << 4),
                         (uint32_t)(((2 + abit) ^ swA) << 4) };
    int rb = wn * 32 + ((lane >> 4) << 3) + (lane & 7);
    int bbit = (lane >> 3) & 1;
    uint32_t bRow = (uint32_t)rb * 64;
    int swB = (rb >> 1) & 3;
    uint32_t colB[2] = { (uint32_t)(((0 + bbit) ^ swB) << 4),
                         (uint32_t)(((2 + bbit) ^ swB) << 4) };

    float acc[4][4][4];
#pragma unroll
    for (int mt = 0; mt < 4; ++mt)
#pragma unroll
        for (int nt = 0; nt < 4; ++nt)
#pragma unroll
            for (int r = 0; r < 4; ++r) acc[mt][nt][r] = 0.f;

    int KkE = Kk;
    if (kcap == 1) KkE = (m0 + TM < Kk) ? m0 + TM : Kk;
    else if (kcap == 2) KkE = (n0 + TN < Kk) ? n0 + TN : Kk;
    const int nc = KkE / KC;

#pragma unroll
    for (int s = 0; s < STAGES - 1; ++s) {
        long long off = (long long)s * KC;
        uint32_t d = sb + s * STAGE_B;
        cpasync16(d + 0 * TILE_B + so0, pAhi + off);
        cpasync16(d + 0 * TILE_B + so1, pAhi + off + 8);
        cpasync16(d + 1 * TILE_B + so0, pAlo + off);
        cpasync16(d + 1 * TILE_B + so1, pAlo + off + 8);
        cpasync16(d + 2 * TILE_B + so0, pBhi + off);
        cpasync16(d + 2 * TILE_B + so1, pBhi + off + 8);
        cpasync16(d + 3 * TILE_B + so0, pBlo + off);
        cpasync16(d + 3 * TILE_B + so1, pBlo + off + 8);
        cp_commit();
    }

    for (int c = 0; c < nc; ++c) {
        cp_wait1();
        __syncthreads();
        if (c + 2 < nc) {
            int st = (c + 2) % STAGES;
            long long off = (long long)(c + 2) * KC;
            uint32_t d = sb + st * STAGE_B;
            cpasync16(d + 0 * TILE_B + so0, pAhi + off);
            cpasync16(d + 0 * TILE_B + so1, pAhi + off + 8);
            cpasync16(d + 1 * TILE_B + so0, pAlo + off);
            cpasync16(d + 1 * TILE_B + so1, pAlo + off + 8);
            cpasync16(d + 2 * TILE_B + so0, pBhi + off);
            cpasync16(d + 2 * TILE_B + so1, pBhi + off + 8);
            cpasync16(d + 3 * TILE_B + so0, pBlo + off);
            cpasync16(d + 3 * TILE_B + so1, pBlo + off + 8);
            cp_commit();
        } else {
            cp_commit();
        }

        uint32_t bA = sb + (c % STAGES) * STAGE_B;
        uint32_t bAhi = bA, bAlo = bA + TILE_B, bBhi = bA + 2 * TILE_B, bBlo = bA + 3 * TILE_B;

#pragma unroll
        for (int kk2 = 0; kk2 < 2; ++kk2) {
            uint32_t ah[4][4], bh[4][2], bl[4][2];
#pragma unroll
            for (int mt = 0; mt < 4; ++mt)
                ldsm4(ah[mt], bAhi + aRow + mt * 1024 + colA[kk2]);
#pragma unroll
            for (int jp = 0; jp < 2; ++jp) {
                uint32_t r[4];
                ldsm4(r, bBhi + bRow + jp * 1024 + colB[kk2]);
                bh[2 * jp][0] = r[0]; bh[2 * jp][1] = r[1];
                bh[2 * jp + 1][0] = r[2]; bh[2 * jp + 1][1] = r[3];
            }
#pragma unroll
            for (int jp = 0; jp < 2; ++jp) {
                uint32_t r[4];
                ldsm4(r, bBlo + bRow + jp * 1024 + colB[kk2]);
                bl[2 * jp][0] = r[0]; bl[2 * jp][1] = r[1];
                bl[2 * jp + 1][0] = r[2]; bl[2 * jp + 1][1] = r[3];
            }
#pragma unroll
            for (int mt = 0; mt < 4; ++mt)
#pragma unroll
                for (int nt = 0; nt < 4; ++nt)
                    mma16816(acc[mt][nt], ah[mt], bh[nt]);

            uint32_t al[4][4];
#pragma unroll
            for (int mt = 0; mt < 4; ++mt)
                ldsm4(al[mt], bAlo + aRow + mt * 1024 + colA[kk2]);
#pragma unroll
            for (int mt = 0; mt < 4; ++mt)
#pragma unroll
                for (int nt = 0; nt < 4; ++nt)
                    mma16816(acc[mt][nt], ah[mt], bl[nt]);
#pragma unroll
            for (int mt = 0; mt < 4; ++mt)
#pragma unroll
                for (int nt = 0; nt < 4; ++nt)
                    mma16816(acc[mt][nt], al[mt], bh[nt]);
        }
    }

    int er = lane >> 2, ec = (lane & 3) * 2;
    if (Cf) {
        float* Cb = Cf + z * sC;
        const float* Rb = Res ? Res + z * sRes : nullptr;
#pragma unroll
        for (int mt = 0; mt < 4; ++mt) {
#pragma unroll
            for (int nt = 0; nt < 4; ++nt) {
                long long r0 = (long long)(m0 + wm * 64 + mt * 16 + er);
                int col = n0 + wn * 32 + nt * 8 + ec;
                float2 v0 = make_float2(acc[mt][nt][0], acc[mt][nt][1]);
                float2 v1 = make_float2(acc[mt][nt][2], acc[mt][nt][3]);
                if (Rb) {
                    float2 q0 = *(const float2*)(Rb + r0 * N + col);
                    float2 q1 = *(const float2*)(Rb + (r0 + 8) * N + col);
                    v0.x += q0.x; v0.y += q0.y; v1.x += q1.x; v1.y += q1.y;
                }
                *(float2*)(Cb + r0 * N + col)       = v0;
                *(float2*)(Cb + (r0 + 8) * N + col) = v1;
            }
        }
    } else {
        bf16* Hb = Chi + z * sC;
        bf16* Lb = Clo + z * sC;
#pragma unroll
        for (int mt = 0; mt < 4; ++mt) {
#pragma unroll
            for (int nt = 0; nt < 4; ++nt) {
                long long r0 = (long long)(m0 + wm * 64 + mt * 16 + er);
                int col = n0 + wn * 32 + nt * 8 + ec;
#pragma unroll
                for (int h = 0; h < 2; ++h) {
                    float v0 = acc[mt][nt][2 * h], v1 = acc[mt][nt][2 * h + 1];
                    long long o = (r0 + 8 * h) * N + col;
                    *(uint32_t*)(Hb + o) = pack_hi(v0, v1);
                    *(uint32_t*)(Lb + o) = pack_lo(v0, v1);
                }
            }
        }
    }
}

// ---------------- row softmax: online max+sum (2 passes), causal ------------
__global__ void softmax_rows(const float* __restrict__ L, bf16* __restrict__ Ahi,
                             bf16* __restrict__ Alo, int Nn, int i_off) {
    int b = blockIdx.y, i = i_off + blockIdx.x;
    const float* row = L + ((long long)b * Nn + i) * Nn;
    bf16* ah = Ahi + ((long long)b * Nn + i) * Nn;
    bf16* al = Alo + ((long long)b * Nn + i) * Nn;
    int nv = i + 1;
    int t = threadIdx.x;
    __shared__ float redm[256], reds[256];

    float m = -1e30f, s = 0.f;
    for (int j = t; j < nv; j += 256) {
        float v = row[j];
        if (v > m) { s = s * __expf(m - v) + 1.f; m = v; }
        else s += __expf(v - m);
    }
    redm[t] = m; reds[t] = s;
    __syncthreads();
    for (int st = 128; st > 0; st >>= 1) {
        if (t < st) {
            float m2 = redm[t + st], s2 = reds[t + st];
            float m1 = redm[t], s1 = reds[t];
            float M = fmaxf(m1, m2);
            redm[t] = M;
            reds[t] = s1 * __expf(m1 - M) + s2 * __expf(m2 - M);
        }
        __syncthreads();
    }
    m = redm[0];
    float inv = 1.f / reds[0];

    for (int j = t; j < nv; j += 256) {
        float v = __expf(row[j] - m) * inv;
        bf16 h = __float2bfloat16(v);
        ah[j] = h;
        al[j] = __float2bfloat16(v - __bfloat162float(h));
    }
    bf16 zz = __float2bfloat16(0.f);
    for (int j = nv + t; j < Nn; j += 256) { ah[j] = zz; al[j] = zz; }
}

// ---------------- launch ----------------------------------------------------
static cudaStream_t make_stream() {
    cudaStream_t s;
    cudaStreamCreateWithFlags(&s, cudaStreamNonBlocking);
    return s;
}
static cudaEvent_t make_event() {
    cudaEvent_t e;
    cudaEventCreateWithFlags(&e, cudaEventDisableTiming);
    return e;
}

extern "C" void kernel_launch(void* const* d_in, const int* in_sizes, int n_in,
                              void* d_out, int out_size) {
    const float* X   = (const float*)d_in[0];
    const float* W_Q = (const float*)d_in[1];
    const float* W_K = (const float*)d_in[2];
    const float* W_V = (const float*)d_in[3];
    const float* W_O = (const float*)d_in[4];
    float* out = (float*)d_out;

    bf16 *Xhi, *Xlo, *XThi, *XTlo, *WQhi, *WQlo, *WKhi, *WKlo;
    bf16 *WOThi, *WOTlo, *WVThi, *WVTlo, *qhi, *qlo, *khi, *klo;
    bf16 *Mhi, *Mlo, *Yhi, *Ylo, *Ahi, *Alo;
    float* L;
    cudaGetSymbolAddress((void**)&Xhi, g_Xhi);     cudaGetSymbolAddress((void**)&Xlo, g_Xlo);
    cudaGetSymbolAddress((void**)&XThi, g_XThi);   cudaGetSymbolAddress((void**)&XTlo, g_XTlo);
    cudaGetSymbolAddress((void**)&WQhi, g_WQhi);   cudaGetSymbolAddress((void**)&WQlo, g_WQlo);
    cudaGetSymbolAddress((void**)&WKhi, g_WKhi);   cudaGetSymbolAddress((void**)&WKlo, g_WKlo);
    cudaGetSymbolAddress((void**)&WOThi, g_WOThi); cudaGetSymbolAddress((void**)&WOTlo, g_WOTlo);
    cudaGetSymbolAddress((void**)&WVThi, g_WVThi); cudaGetSymbolAddress((void**)&WVTlo, g_WVTlo);
    cudaGetSymbolAddress((void**)&qhi, g_qhi);     cudaGetSymbolAddress((void**)&qlo, g_qlo);
    cudaGetSymbolAddress((void**)&khi, g_khi);     cudaGetSymbolAddress((void**)&klo, g_klo);
    cudaGetSymbolAddress((void**)&Mhi, g_Mhi);     cudaGetSymbolAddress((void**)&Mlo, g_Mlo);
    cudaGetSymbolAddress((void**)&Yhi, g_Yhi);     cudaGetSymbolAddress((void**)&Ylo, g_Ylo);
    cudaGetSymbolAddress((void**)&Ahi, g_Ahi);     cudaGetSymbolAddress((void**)&Alo, g_Alo);
    cudaGetSymbolAddress((void**)&L, g_L);

    cudaFuncSetAttribute(hgemm, cudaFuncAttributeMaxDynamicSharedMemorySize, GSMEM);

    static cudaStream_t s1 = make_stream();   // weights/M'/Y + H-half branch
    static cudaStream_t s2 = make_stream();   // W_K/k + logits-L branch
    static cudaEvent_t evRoot = make_event(); // capture fork point
    static cudaEvent_t evX  = make_event();   // X conversion done
    static cudaEvent_t evQ  = make_event();   // q-projection done
    static cudaEvent_t evK  = make_event();   // k-projection done
    static cudaEvent_t evLH = make_event();   // logits-H done
    static cudaEvent_t evLL = make_event();   // logits-L done
    static cudaEvent_t evY  = make_event();   // Y = M'X done
    static cudaEvent_t evOH = make_event();   // out-H done

    const long long sX  = (long long)DDIM * NSEQ;
    const long long sXT = (long long)NSEQ * DDIM;
    const long long sQ  = (long long)NSEQ * KDIM;
    const long long sL  = (long long)NSEQ * NSEQ;
    const int HALF = NSEQ / 2;

    dim3 tb(32, 8);
    cudaEventRecord(evRoot, 0);
    cudaStreamWaitEvent(s1, evRoot, 0);
    cudaStreamWaitEvent(s2, evRoot, 0);

    // s1: W_O/W_V transposes -> M' -> Y = M'.X (pre-softmax)
    transpose_hl<<<dim3(DDIM / 32, KDIM / 32, 1), tb, 0, s1>>>(W_O, WOThi, WOTlo, KDIM, DDIM, 0, 0);
    transpose_hl<<<dim3(DDIM / 32, KDIM / 32, 1), tb, 0, s1>>>(W_V, WVThi, WVTlo, KDIM, DDIM, 0, 0);
    hgemm<<<dim3(DDIM / TN, DDIM / TM, 1), 256, GSMEM, s1>>>(
        WOThi, WOTlo, WVThi, WVTlo, nullptr, Mhi, Mlo, nullptr,
        DDIM, DDIM, KDIM, KDIM, KDIM, 0, 0, 0, 0, 0, 0, 0, 0);

    // s2: W_K convert
    convert_hl<<<(KDIM * DDIM / 4) / 256, 256, 0, s2>>>(W_K, WKhi, WKlo, (long long)KDIM * DDIM);

    // s0: X conversion + W_Q convert
    convtrans_X<<<dim3(NSEQ / 32, DDIM / 32, BATCH), tb>>>(X, Xhi, Xlo, XThi, XTlo);
    cudaEventRecord(evX, 0);
    convert_hl<<<(KDIM * DDIM / 4) / 256, 256>>>(W_Q, WQhi, WQlo, (long long)KDIM * DDIM);

    // s1: Y[b][d][t] = sum_e M'[d][e] * XT[t][e]
    cudaStreamWaitEvent(s1, evX, 0);
    hgemm<<<dim3(NSEQ / TN, DDIM / TM, BATCH), 256, GSMEM, s1>>>(
        Mhi, Mlo, XThi, XTlo, nullptr, Yhi, Ylo, nullptr,
        DDIM, NSEQ, DDIM, DDIM, DDIM, 0, sXT, sX, 0, 0, 0, 0, 0);
    cudaEventRecord(evY, s1);

    // s2: k-projection
    cudaStreamWaitEvent(s2, evX, 0);
    hgemm<<<dim3(KDIM / TN, NSEQ / TM, BATCH), 256, GSMEM, s2>>>(
        XThi, XTlo, WKhi, WKlo, nullptr, khi, klo, nullptr,
        NSEQ, KDIM, DDIM, DDIM, DDIM, sXT, 0, sQ, 0, 0, 0, 0, 0);
    cudaEventRecord(evK, s2);

    // s0: q-projection
    hgemm<<<dim3(KDIM / TN, NSEQ / TM, BATCH), 256, GSMEM>>>(
        XThi, XTlo, WQhi, WQlo, nullptr, qhi, qlo, nullptr,
        NSEQ, KDIM, DDIM, DDIM, DDIM, sXT, 0, sQ, 0, 0, 0, 0, 0);
    cudaEventRecord(evQ, 0);

    // s0: logits-H (rows [1024,2048)) after k ready; launched FIRST so its
    // CTAs dispatch ahead of logits-L's
    cudaStreamWaitEvent(0, evK, 0);
    hgemm<<<dim3(NSEQ / TN, HALF / TM, BATCH), 256, GSMEM>>>(
        qhi, qlo, khi, klo, L, nullptr, nullptr, nullptr,
        NSEQ, NSEQ, KDIM, KDIM, KDIM, sQ, sQ, sL, 0, 1, 0, HALF, 0);
    cudaEventRecord(evLH, 0);

    // s2: logits-L (rows [0,1024)) concurrent with logits-H — backfills its
    // partial last wave (k ordered on s2; q via evQ)
    cudaStreamWaitEvent(s2, evQ, 0);
    hgemm<<<dim3(NSEQ / TN, HALF / TM, BATCH), 256, GSMEM, s2>>>(
        qhi, qlo, khi, klo, L, nullptr, nullptr, nullptr,
        NSEQ, NSEQ, KDIM, KDIM, KDIM, sQ, sQ, sL, 0, 1, 0, 0, 0);
    cudaEventRecord(evLL, s2);

    // s1 branch: softmax-H -> out-H (Y already ordered on s1)
    cudaStreamWaitEvent(s1, evLH, 0);
    softmax_rows<<<dim3(HALF, BATCH), 256, 0, s1>>>(L, Ahi, Alo, NSEQ, HALF);
    hgemm<<<dim3(HALF / TN, DDIM / TM, BATCH), 256, GSMEM, s1>>>(
        Yhi, Ylo, Ahi, Alo, out, nullptr, nullptr, X,
        DDIM, NSEQ, NSEQ, NSEQ, NSEQ, sX, sL, sX, sX, 0, 2, 0, HALF);
    cudaEventRecord(evOH, s1);

    // s0: softmax-L -> out-L (wait logits-L from s2, Y from s1)
    cudaStreamWaitEvent(0, evLL, 0);
    softmax_rows<<<dim3(HALF, BATCH), 256>>>(L, Ahi, Alo, NSEQ, 0);
    cudaStreamWaitEvent(0, evY, 0);
    hgemm<<<dim3(HALF / TN, DDIM / TM, BATCH), 256, GSMEM>>>(
        Yhi, Ylo, Ahi, Alo, out, nullptr, nullptr, X,
        DDIM, NSEQ, NSEQ, NSEQ, NSEQ, sX, sL, sX, sX, 0, 2, 0, 0);

    cudaStreamWaitEvent(0, evOH, 0);
}